// round 5
// baseline (speedup 1.0000x reference)
#include <cuda_runtime.h>

// PBC neighbor-list distances. Two launches:
//   1) transpose positions AoS [N,3] -> device SoA xs/ys/zs (coalesced reloads)
//   2) fused grid (N, S+1): shifted-image rows (float4 quads) + triangle rows
// Output (float32): [ d2[P] | mask_c0[P] | mask_c1[P] | ... ],
//   P = N*(N-1)/2 + S*N*N. All offsets fit in int32.

#define MAXN 4096

__device__ float g_xs[MAXN];
__device__ float g_ys[MAXN];
__device__ float g_zs[MAXN];

__global__ void transpose_kernel(const float* __restrict__ pos, int n)
{
    int j = blockIdx.x * blockDim.x + threadIdx.x;
    if (j < n) {
        g_xs[j] = pos[3 * j + 0];
        g_ys[j] = pos[3 * j + 1];
        g_zs[j] = pos[3 * j + 2];
    }
}

template <int C>
__global__ __launch_bounds__(256, 8)
void fused_kernel(const float* __restrict__ cell,
                  const float* __restrict__ shifts,
                  const float* __restrict__ cutoffs,
                  int n, int S, int Pc, int P,
                  float* __restrict__ out)
{
    int i   = blockIdx.x;
    int s   = blockIdx.y;
    int tid = threadIdx.x;

    float c2[C];
#pragma unroll
    for (int c = 0; c < C; c++) { float cv = cutoffs[c]; c2[c] = cv * cv; }

    float pix = g_xs[i];
    float piy = g_ys[i];
    float piz = g_zs[i];

    if (s < S) {
        // ---------------- shifted-image row (s, i, :) ----------------
        float s0 = shifts[3 * s + 0], s1 = shifts[3 * s + 1], s2 = shifts[3 * s + 2];
        float svx = s0 * cell[0] + s1 * cell[3] + s2 * cell[6];
        float svy = s0 * cell[1] + s1 * cell[4] + s2 * cell[7];
        float svz = s0 * cell[2] + s1 * cell[5] + s2 * cell[8];

        int rowbase = Pc + (s * n + i) * n;
        const float4* __restrict__ xs4 = (const float4*)g_xs;
        const float4* __restrict__ ys4 = (const float4*)g_ys;
        const float4* __restrict__ zs4 = (const float4*)g_zs;
        int nq = n >> 2;

        for (int q = tid; q < nq; q += blockDim.x) {
            float4 xv = xs4[q];
            float4 yv = ys4[q];
            float4 zv = zs4[q];

            float dx, dy, dz;
            float4 dv;
            // reference FP ordering: (pi - pj) + sv
            dx = (pix - xv.x) + svx; dy = (piy - yv.x) + svy; dz = (piz - zv.x) + svz;
            dv.x = dx * dx + dy * dy + dz * dz;
            dx = (pix - xv.y) + svx; dy = (piy - yv.y) + svy; dz = (piz - zv.y) + svz;
            dv.y = dx * dx + dy * dy + dz * dz;
            dx = (pix - xv.z) + svx; dy = (piy - yv.z) + svy; dz = (piz - zv.z) + svz;
            dv.z = dx * dx + dy * dy + dz * dz;
            dx = (pix - xv.w) + svx; dy = (piy - yv.w) + svy; dz = (piz - zv.w) + svz;
            dv.w = dx * dx + dy * dy + dz * dz;

            int addr = rowbase + 4 * q;
            *(float4*)(out + addr) = dv;

#pragma unroll
            for (int c = 0; c < C; c++) {
                float4 mv;
                mv.x = (dv.x < c2[c]) ? 1.0f : 0.0f;
                mv.y = (dv.y < c2[c]) ? 1.0f : 0.0f;
                mv.z = (dv.z < c2[c]) ? 1.0f : 0.0f;
                mv.w = (dv.w < c2[c]) ? 1.0f : 0.0f;
                *(float4*)(out + P + c * P + addr) = mv;
            }
        }

        // scalar remainder (n % 4 != 0; not hit for n=1000)
        for (int j = (nq << 2) + tid; j < n; j += blockDim.x) {
            float dx = (pix - g_xs[j]) + svx;
            float dy = (piy - g_ys[j]) + svy;
            float dz = (piz - g_zs[j]) + svz;
            float d2 = dx * dx + dy * dy + dz * dz;
            int addr = rowbase + j;
            out[addr] = d2;
#pragma unroll
            for (int c = 0; c < C; c++)
                out[P + c * P + addr] = (d2 < c2[c]) ? 1.0f : 0.0f;
        }
    } else {
        // ---------------- triangle row i: pairs (i, j), j > i ----------------
        int off = i * (2 * n - i - 1) / 2;   // packed row start
        for (int j = i + 1 + tid; j < n; j += blockDim.x) {
            float dx = pix - g_xs[j];
            float dy = piy - g_ys[j];
            float dz = piz - g_zs[j];
            float d2 = dx * dx + dy * dy + dz * dz;
            int p = off + (j - i - 1);
            out[p] = d2;
#pragma unroll
            for (int c = 0; c < C; c++)
                out[P + c * P + p] = (d2 < c2[c]) ? 1.0f : 0.0f;
        }
    }
}

extern "C" void kernel_launch(void* const* d_in, const int* in_sizes, int n_in,
                              void* d_out, int out_size)
{
    const float* pos     = (const float*)d_in[0];  // [N,3]
    const float* cell    = (const float*)d_in[1];  // [3,3]
    const float* shifts  = (const float*)d_in[2];  // [S,3]
    const float* cutoffs = (const float*)d_in[3];  // [C]

    int n = in_sizes[0] / 3;
    if (n > MAXN) n = MAXN;
    int S = in_sizes[2] / 3;
    int C = in_sizes[3];

    int Pc = n * (n - 1) / 2;
    int P  = Pc + S * n * n;

    transpose_kernel<<<(n + 255) / 256, 256>>>(pos, n);

    dim3 grid(n, S + 1);
    float* out = (float*)d_out;

    switch (C) {
        case 1: fused_kernel<1><<<grid, 256>>>(cell, shifts, cutoffs, n, S, Pc, P, out); break;
        case 2: fused_kernel<2><<<grid, 256>>>(cell, shifts, cutoffs, n, S, Pc, P, out); break;
        case 3: fused_kernel<3><<<grid, 256>>>(cell, shifts, cutoffs, n, S, Pc, P, out); break;
        default: fused_kernel<4><<<grid, 256>>>(cell, shifts, cutoffs, n, S, Pc, P, out); break;
    }
}

// round 6
// speedup vs baseline: 1.0779x; 1.0779x over previous
#include <cuda_runtime.h>

// PBC neighbor-list distances. Single fused launch.
// Output (float32): [ d2[P] | mask_c0[P] | mask_c1[P] | ... ]
//   P = N*(N-1)/2 + S*N*N
// gridDim = (ceil(N/2), S+1):
//   y = s < S : shifted rows (s, i0, :) and (s, i1, :), i0=2bx, i1=2bx+1.
//               One float4 j-quad per thread, reused for both rows ->
//               3 LDG.128 feed 6 independent STG.128 streams (2x store MLP).
//   y = S     : triangle rows i0, i1 — scalar strided (3.7% of bytes).
// All offsets fit in int32 (3P ~ 40.5M).

template <int C>
__global__ __launch_bounds__(256, 8)
void fused_kernel(const float* __restrict__ pos,
                  const float* __restrict__ cell,
                  const float* __restrict__ shifts,
                  const float* __restrict__ cutoffs,
                  int n, int S, int Pc, int P,
                  float* __restrict__ out)
{
    int bx  = blockIdx.x;
    int s   = blockIdx.y;
    int tid = threadIdx.x;

    int i0 = 2 * bx;
    int i1 = i0 + 1;
    bool has_i1 = (i1 < n);

    float c2[C];
#pragma unroll
    for (int c = 0; c < C; c++) { float cv = cutoffs[c]; c2[c] = cv * cv; }

    float p0x = pos[3 * i0 + 0], p0y = pos[3 * i0 + 1], p0z = pos[3 * i0 + 2];
    float p1x = p0x, p1y = p0y, p1z = p0z;
    if (has_i1) { p1x = pos[3 * i1 + 0]; p1y = pos[3 * i1 + 1]; p1z = pos[3 * i1 + 2]; }

    if (s < S) {
        // ---------------- shifted-image rows (s, i0/i1, :) ----------------
        float s0 = shifts[3 * s + 0], s1 = shifts[3 * s + 1], s2 = shifts[3 * s + 2];
        float svx = s0 * cell[0] + s1 * cell[3] + s2 * cell[6];
        float svy = s0 * cell[1] + s1 * cell[4] + s2 * cell[7];
        float svz = s0 * cell[2] + s1 * cell[5] + s2 * cell[8];

        int row0 = Pc + (s * n + i0) * n;
        int row1 = row0 + n;
        const float4* __restrict__ pos4 = (const float4*)pos;
        int nq = n >> 2;

        for (int q = tid; q < nq; q += blockDim.x) {
            float4 a  = pos4[3 * q + 0];
            float4 b  = pos4[3 * q + 1];
            float4 cc = pos4[3 * q + 2];

            float jx0 = a.x,  jy0 = a.y,  jz0 = a.z;
            float jx1 = a.w,  jy1 = b.x,  jz1 = b.y;
            float jx2 = b.z,  jy2 = b.w,  jz2 = cc.x;
            float jx3 = cc.y, jy3 = cc.z, jz3 = cc.w;

            float dx, dy, dz;

            // ---- row i0 ----
            float4 dv;
            dx = (p0x - jx0) + svx; dy = (p0y - jy0) + svy; dz = (p0z - jz0) + svz;
            dv.x = dx * dx + dy * dy + dz * dz;
            dx = (p0x - jx1) + svx; dy = (p0y - jy1) + svy; dz = (p0z - jz1) + svz;
            dv.y = dx * dx + dy * dy + dz * dz;
            dx = (p0x - jx2) + svx; dy = (p0y - jy2) + svy; dz = (p0z - jz2) + svz;
            dv.z = dx * dx + dy * dy + dz * dz;
            dx = (p0x - jx3) + svx; dy = (p0y - jy3) + svy; dz = (p0z - jz3) + svz;
            dv.w = dx * dx + dy * dy + dz * dz;

            int a0 = row0 + 4 * q;
            *(float4*)(out + a0) = dv;
#pragma unroll
            for (int c = 0; c < C; c++) {
                float4 mv;
                mv.x = (dv.x < c2[c]) ? 1.0f : 0.0f;
                mv.y = (dv.y < c2[c]) ? 1.0f : 0.0f;
                mv.z = (dv.z < c2[c]) ? 1.0f : 0.0f;
                mv.w = (dv.w < c2[c]) ? 1.0f : 0.0f;
                *(float4*)(out + P + c * P + a0) = mv;
            }

            // ---- row i1 ----
            if (has_i1) {
                float4 ev;
                dx = (p1x - jx0) + svx; dy = (p1y - jy0) + svy; dz = (p1z - jz0) + svz;
                ev.x = dx * dx + dy * dy + dz * dz;
                dx = (p1x - jx1) + svx; dy = (p1y - jy1) + svy; dz = (p1z - jz1) + svz;
                ev.y = dx * dx + dy * dy + dz * dz;
                dx = (p1x - jx2) + svx; dy = (p1y - jy2) + svy; dz = (p1z - jz2) + svz;
                ev.z = dx * dx + dy * dy + dz * dz;
                dx = (p1x - jx3) + svx; dy = (p1y - jy3) + svy; dz = (p1z - jz3) + svz;
                ev.w = dx * dx + dy * dy + dz * dz;

                int a1 = row1 + 4 * q;
                *(float4*)(out + a1) = ev;
#pragma unroll
                for (int c = 0; c < C; c++) {
                    float4 mv;
                    mv.x = (ev.x < c2[c]) ? 1.0f : 0.0f;
                    mv.y = (ev.y < c2[c]) ? 1.0f : 0.0f;
                    mv.z = (ev.z < c2[c]) ? 1.0f : 0.0f;
                    mv.w = (ev.w < c2[c]) ? 1.0f : 0.0f;
                    *(float4*)(out + P + c * P + a1) = mv;
                }
            }
        }

        // scalar remainder (n % 4 != 0; not hit for n=1000)
        for (int j = (nq << 2) + tid; j < n; j += blockDim.x) {
            float jx = pos[3 * j + 0], jy = pos[3 * j + 1], jz = pos[3 * j + 2];
            {
                float dx = (p0x - jx) + svx, dy = (p0y - jy) + svy, dz = (p0z - jz) + svz;
                float d2 = dx * dx + dy * dy + dz * dz;
                int addr = row0 + j;
                out[addr] = d2;
#pragma unroll
                for (int c = 0; c < C; c++)
                    out[P + c * P + addr] = (d2 < c2[c]) ? 1.0f : 0.0f;
            }
            if (has_i1) {
                float dx = (p1x - jx) + svx, dy = (p1y - jy) + svy, dz = (p1z - jz) + svz;
                float d2 = dx * dx + dy * dy + dz * dz;
                int addr = row1 + j;
                out[addr] = d2;
#pragma unroll
                for (int c = 0; c < C; c++)
                    out[P + c * P + addr] = (d2 < c2[c]) ? 1.0f : 0.0f;
            }
        }
    } else {
        // ---------------- triangle rows i0, i1 ----------------
        int off0 = i0 * (2 * n - i0 - 1) / 2;
        for (int j = i0 + 1 + tid; j < n; j += blockDim.x) {
            float dx = p0x - pos[3 * j + 0];
            float dy = p0y - pos[3 * j + 1];
            float dz = p0z - pos[3 * j + 2];
            float d2 = dx * dx + dy * dy + dz * dz;
            int p = off0 + (j - i0 - 1);
            out[p] = d2;
#pragma unroll
            for (int c = 0; c < C; c++)
                out[P + c * P + p] = (d2 < c2[c]) ? 1.0f : 0.0f;
        }
        if (has_i1) {
            int off1 = i1 * (2 * n - i1 - 1) / 2;
            for (int j = i1 + 1 + tid; j < n; j += blockDim.x) {
                float dx = p1x - pos[3 * j + 0];
                float dy = p1y - pos[3 * j + 1];
                float dz = p1z - pos[3 * j + 2];
                float d2 = dx * dx + dy * dy + dz * dz;
                int p = off1 + (j - i1 - 1);
                out[p] = d2;
#pragma unroll
                for (int c = 0; c < C; c++)
                    out[P + c * P + p] = (d2 < c2[c]) ? 1.0f : 0.0f;
            }
        }
    }
}

extern "C" void kernel_launch(void* const* d_in, const int* in_sizes, int n_in,
                              void* d_out, int out_size)
{
    const float* pos     = (const float*)d_in[0];  // [N,3]
    const float* cell    = (const float*)d_in[1];  // [3,3]
    const float* shifts  = (const float*)d_in[2];  // [S,3]
    const float* cutoffs = (const float*)d_in[3];  // [C]

    int n = in_sizes[0] / 3;
    int S = in_sizes[2] / 3;
    int C = in_sizes[3];

    int Pc = n * (n - 1) / 2;
    int P  = Pc + S * n * n;

    dim3 grid((n + 1) / 2, S + 1);
    float* out = (float*)d_out;

    switch (C) {
        case 1: fused_kernel<1><<<grid, 256>>>(pos, cell, shifts, cutoffs, n, S, Pc, P, out); break;
        case 2: fused_kernel<2><<<grid, 256>>>(pos, cell, shifts, cutoffs, n, S, Pc, P, out); break;
        case 3: fused_kernel<3><<<grid, 256>>>(pos, cell, shifts, cutoffs, n, S, Pc, P, out); break;
        default: fused_kernel<4><<<grid, 256>>>(pos, cell, shifts, cutoffs, n, S, Pc, P, out); break;
    }
}

// round 7
// speedup vs baseline: 1.0790x; 1.0011x over previous
#include <cuda_runtime.h>

// PBC neighbor-list distances. Single fused launch, packed f32x2 math.
// Output (float32): [ d2[P] | mask_c0[P] | mask_c1[P] | ... ]
//   P = N*(N-1)/2 + S*N*N
// gridDim = (N, S+1): y=s<S shifted row (one float4 j-quad per thread),
//                     y=S triangle row (scalar, 3.7% of bytes).
// All offsets fit in int32 (3P ~ 40.5M).

typedef unsigned long long u64;

__device__ __forceinline__ u64 pk2(float lo, float hi) {
    u64 r; asm("mov.b64 %0,{%1,%2};" : "=l"(r) : "f"(lo), "f"(hi)); return r;
}
__device__ __forceinline__ void upk2(u64 v, float& lo, float& hi) {
    asm("mov.b64 {%0,%1},%2;" : "=f"(lo), "=f"(hi) : "l"(v));
}
__device__ __forceinline__ u64 fma2(u64 a, u64 b, u64 c) {
    u64 r; asm("fma.rn.f32x2 %0,%1,%2,%3;" : "=l"(r) : "l"(a), "l"(b), "l"(c)); return r;
}
__device__ __forceinline__ u64 add2(u64 a, u64 b) {
    u64 r; asm("add.rn.f32x2 %0,%1,%2;" : "=l"(r) : "l"(a), "l"(b)); return r;
}
__device__ __forceinline__ u64 mul2(u64 a, u64 b) {
    u64 r; asm("mul.rn.f32x2 %0,%1,%2;" : "=l"(r) : "l"(a), "l"(b)); return r;
}

template <int C>
__global__ __launch_bounds__(256, 8)
void fused_kernel(const float* __restrict__ pos,
                  const float* __restrict__ cell,
                  const float* __restrict__ shifts,
                  const float* __restrict__ cutoffs,
                  int n, int S, int Pc, int P,
                  float* __restrict__ out)
{
    int i   = blockIdx.x;
    int s   = blockIdx.y;
    int tid = threadIdx.x;

    float c2[C];
#pragma unroll
    for (int c = 0; c < C; c++) { float cv = cutoffs[c]; c2[c] = cv * cv; }

    float pix = pos[3 * i + 0];
    float piy = pos[3 * i + 1];
    float piz = pos[3 * i + 2];

    if (s < S) {
        // ---------------- shifted-image row (s, i, :) ----------------
        float s0 = shifts[3 * s + 0], s1 = shifts[3 * s + 1], s2 = shifts[3 * s + 2];
        float svx = s0 * cell[0] + s1 * cell[3] + s2 * cell[6];
        float svy = s0 * cell[1] + s1 * cell[4] + s2 * cell[7];
        float svz = s0 * cell[2] + s1 * cell[5] + s2 * cell[8];

        // broadcast pairs (hoisted)
        u64 PX = pk2(pix, pix), PY = pk2(piy, piy), PZ = pk2(piz, piz);
        u64 SX = pk2(svx, svx), SY = pk2(svy, svy), SZ = pk2(svz, svz);
        u64 NEG1 = pk2(-1.0f, -1.0f);

        int rowbase = Pc + (s * n + i) * n;
        const float4* __restrict__ pos4 = (const float4*)pos;
        int nq = n >> 2;

        for (int q = tid; q < nq; q += blockDim.x) {
            float4 a  = pos4[3 * q + 0];
            float4 b  = pos4[3 * q + 1];
            float4 cc = pos4[3 * q + 2];

            // j components: x = {a.x, a.w, b.z, cc.y}
            //               y = {a.y, b.x, b.w, cc.z}
            //               z = {a.z, b.y, cc.x, cc.w}
            u64 JX01 = pk2(a.x, a.w), JX23 = pk2(b.z, cc.y);
            u64 JY01 = pk2(a.y, b.x), JY23 = pk2(b.w, cc.z);
            u64 JZ01 = pk2(a.z, b.y), JZ23 = pk2(cc.x, cc.w);

            // dx = (pi - pj) + sv : fma(pj, -1, pi) is bitwise (pi - pj)
            u64 DX01 = add2(fma2(JX01, NEG1, PX), SX);
            u64 DX23 = add2(fma2(JX23, NEG1, PX), SX);
            u64 DY01 = add2(fma2(JY01, NEG1, PY), SY);
            u64 DY23 = add2(fma2(JY23, NEG1, PY), SY);
            u64 DZ01 = add2(fma2(JZ01, NEG1, PZ), SZ);
            u64 DZ23 = add2(fma2(JZ23, NEG1, PZ), SZ);

            u64 D01 = fma2(DX01, DX01, fma2(DY01, DY01, mul2(DZ01, DZ01)));
            u64 D23 = fma2(DX23, DX23, fma2(DY23, DY23, mul2(DZ23, DZ23)));

            float4 dv;
            upk2(D01, dv.x, dv.y);
            upk2(D23, dv.z, dv.w);

            int addr = rowbase + 4 * q;
            *(float4*)(out + addr) = dv;

#pragma unroll
            for (int c = 0; c < C; c++) {
                float4 mv;
                mv.x = (dv.x < c2[c]) ? 1.0f : 0.0f;
                mv.y = (dv.y < c2[c]) ? 1.0f : 0.0f;
                mv.z = (dv.z < c2[c]) ? 1.0f : 0.0f;
                mv.w = (dv.w < c2[c]) ? 1.0f : 0.0f;
                *(float4*)(out + P + c * P + addr) = mv;
            }
        }

        // scalar remainder (n % 4 != 0; not hit for n=1000)
        for (int j = (nq << 2) + tid; j < n; j += blockDim.x) {
            float dx = (pix - pos[3 * j + 0]) + svx;
            float dy = (piy - pos[3 * j + 1]) + svy;
            float dz = (piz - pos[3 * j + 2]) + svz;
            float d2 = dx * dx + dy * dy + dz * dz;
            int addr = rowbase + j;
            out[addr] = d2;
#pragma unroll
            for (int c = 0; c < C; c++)
                out[P + c * P + addr] = (d2 < c2[c]) ? 1.0f : 0.0f;
        }
    } else {
        // ---------------- triangle row i: pairs (i, j), j > i ----------------
        int off = i * (2 * n - i - 1) / 2;   // packed row start
        for (int j = i + 1 + tid; j < n; j += blockDim.x) {
            float dx = pix - pos[3 * j + 0];
            float dy = piy - pos[3 * j + 1];
            float dz = piz - pos[3 * j + 2];
            float d2 = dx * dx + dy * dy + dz * dz;
            int p = off + (j - i - 1);
            out[p] = d2;
#pragma unroll
            for (int c = 0; c < C; c++)
                out[P + c * P + p] = (d2 < c2[c]) ? 1.0f : 0.0f;
        }
    }
}

extern "C" void kernel_launch(void* const* d_in, const int* in_sizes, int n_in,
                              void* d_out, int out_size)
{
    const float* pos     = (const float*)d_in[0];  // [N,3]
    const float* cell    = (const float*)d_in[1];  // [3,3]
    const float* shifts  = (const float*)d_in[2];  // [S,3]
    const float* cutoffs = (const float*)d_in[3];  // [C]

    int n = in_sizes[0] / 3;
    int S = in_sizes[2] / 3;
    int C = in_sizes[3];

    int Pc = n * (n - 1) / 2;
    int P  = Pc + S * n * n;

    dim3 grid(n, S + 1);
    float* out = (float*)d_out;

    switch (C) {
        case 1: fused_kernel<1><<<grid, 256>>>(pos, cell, shifts, cutoffs, n, S, Pc, P, out); break;
        case 2: fused_kernel<2><<<grid, 256>>>(pos, cell, shifts, cutoffs, n, S, Pc, P, out); break;
        case 3: fused_kernel<3><<<grid, 256>>>(pos, cell, shifts, cutoffs, n, S, Pc, P, out); break;
        default: fused_kernel<4><<<grid, 256>>>(pos, cell, shifts, cutoffs, n, S, Pc, P, out); break;
    }
}

// round 8
// speedup vs baseline: 1.1592x; 1.0743x over previous
#include <cuda_runtime.h>

// PBC neighbor-list distances. Single fused launch.
// Output (float32): [ d2[P] | mask_c0[P] | mask_c1[P] | ... ]
//   P = N*(N-1)/2 + S*N*N
// gridDim = (N, S+1): y=s<S shifted row (one float4 j-quad per thread),
//                     y=S triangle row (scalar, 3.7% of bytes).
// Output is write-once streaming -> st.global.cs (evict-first) to avoid
// thrashing L2 with a 162MB write-allocate stream.
// All offsets fit in int32 (3P ~ 40.5M).

__device__ __forceinline__ void st_cs_v4(float* p, float4 v) {
    asm volatile("st.global.cs.v4.f32 [%0],{%1,%2,%3,%4};"
                 :: "l"(p), "f"(v.x), "f"(v.y), "f"(v.z), "f"(v.w) : "memory");
}
__device__ __forceinline__ void st_cs_f(float* p, float v) {
    asm volatile("st.global.cs.f32 [%0],%1;" :: "l"(p), "f"(v) : "memory");
}

template <int C>
__global__ __launch_bounds__(256)
void fused_kernel(const float* __restrict__ pos,
                  const float* __restrict__ cell,
                  const float* __restrict__ shifts,
                  const float* __restrict__ cutoffs,
                  int n, int S, int Pc, int P,
                  float* __restrict__ out)
{
    int i   = blockIdx.x;
    int s   = blockIdx.y;
    int tid = threadIdx.x;

    float c2[C];
#pragma unroll
    for (int c = 0; c < C; c++) { float cv = cutoffs[c]; c2[c] = cv * cv; }

    float pix = pos[3 * i + 0];
    float piy = pos[3 * i + 1];
    float piz = pos[3 * i + 2];

    if (s < S) {
        // ---------------- shifted-image row (s, i, :) ----------------
        float s0 = shifts[3 * s + 0], s1 = shifts[3 * s + 1], s2 = shifts[3 * s + 2];
        float svx = s0 * cell[0] + s1 * cell[3] + s2 * cell[6];
        float svy = s0 * cell[1] + s1 * cell[4] + s2 * cell[7];
        float svz = s0 * cell[2] + s1 * cell[5] + s2 * cell[8];

        int rowbase = Pc + (s * n + i) * n;
        const float4* __restrict__ pos4 = (const float4*)pos;
        int nq = n >> 2;

        for (int q = tid; q < nq; q += blockDim.x) {
            float4 a  = pos4[3 * q + 0];
            float4 b  = pos4[3 * q + 1];
            float4 cc = pos4[3 * q + 2];

            float dx, dy, dz;
            float4 dv;
            // reference FP ordering: (pi - pj) + sv
            dx = (pix - a.x) + svx;  dy = (piy - a.y) + svy;  dz = (piz - a.z) + svz;
            dv.x = dx * dx + dy * dy + dz * dz;
            dx = (pix - a.w) + svx;  dy = (piy - b.x) + svy;  dz = (piz - b.y) + svz;
            dv.y = dx * dx + dy * dy + dz * dz;
            dx = (pix - b.z) + svx;  dy = (piy - b.w) + svy;  dz = (piz - cc.x) + svz;
            dv.z = dx * dx + dy * dy + dz * dz;
            dx = (pix - cc.y) + svx; dy = (piy - cc.z) + svy; dz = (piz - cc.w) + svz;
            dv.w = dx * dx + dy * dy + dz * dz;

            int addr = rowbase + 4 * q;
            st_cs_v4(out + addr, dv);

#pragma unroll
            for (int c = 0; c < C; c++) {
                float4 mv;
                mv.x = (dv.x < c2[c]) ? 1.0f : 0.0f;
                mv.y = (dv.y < c2[c]) ? 1.0f : 0.0f;
                mv.z = (dv.z < c2[c]) ? 1.0f : 0.0f;
                mv.w = (dv.w < c2[c]) ? 1.0f : 0.0f;
                st_cs_v4(out + P + c * P + addr, mv);
            }
        }

        // scalar remainder (n % 4 != 0; not hit for n=1000)
        for (int j = (nq << 2) + tid; j < n; j += blockDim.x) {
            float dx = (pix - pos[3 * j + 0]) + svx;
            float dy = (piy - pos[3 * j + 1]) + svy;
            float dz = (piz - pos[3 * j + 2]) + svz;
            float d2 = dx * dx + dy * dy + dz * dz;
            int addr = rowbase + j;
            st_cs_f(out + addr, d2);
#pragma unroll
            for (int c = 0; c < C; c++)
                st_cs_f(out + P + c * P + addr, (d2 < c2[c]) ? 1.0f : 0.0f);
        }
    } else {
        // ---------------- triangle row i: pairs (i, j), j > i ----------------
        int off = i * (2 * n - i - 1) / 2;   // packed row start
        for (int j = i + 1 + tid; j < n; j += blockDim.x) {
            float dx = pix - pos[3 * j + 0];
            float dy = piy - pos[3 * j + 1];
            float dz = piz - pos[3 * j + 2];
            float d2 = dx * dx + dy * dy + dz * dz;
            int p = off + (j - i - 1);
            st_cs_f(out + p, d2);
#pragma unroll
            for (int c = 0; c < C; c++)
                st_cs_f(out + P + c * P + p, (d2 < c2[c]) ? 1.0f : 0.0f);
        }
    }
}

extern "C" void kernel_launch(void* const* d_in, const int* in_sizes, int n_in,
                              void* d_out, int out_size)
{
    const float* pos     = (const float*)d_in[0];  // [N,3]
    const float* cell    = (const float*)d_in[1];  // [3,3]
    const float* shifts  = (const float*)d_in[2];  // [S,3]
    const float* cutoffs = (const float*)d_in[3];  // [C]

    int n = in_sizes[0] / 3;
    int S = in_sizes[2] / 3;
    int C = in_sizes[3];

    int Pc = n * (n - 1) / 2;
    int P  = Pc + S * n * n;

    dim3 grid(n, S + 1);
    float* out = (float*)d_out;

    switch (C) {
        case 1: fused_kernel<1><<<grid, 256>>>(pos, cell, shifts, cutoffs, n, S, Pc, P, out); break;
        case 2: fused_kernel<2><<<grid, 256>>>(pos, cell, shifts, cutoffs, n, S, Pc, P, out); break;
        case 3: fused_kernel<3><<<grid, 256>>>(pos, cell, shifts, cutoffs, n, S, Pc, P, out); break;
        default: fused_kernel<4><<<grid, 256>>>(pos, cell, shifts, cutoffs, n, S, Pc, P, out); break;
    }
}